// round 15
// baseline (speedup 1.0000x reference)
#include <cuda_runtime.h>
#include <math.h>

#define BNq 1024
#define SCALEF 0.17677669529663687f   // 32^-0.5

typedef unsigned long long ull;

// ---------------- scratch (device globals; no allocation allowed) ----------
__device__ __align__(16) float g_q [BNq * 256];        // [bi][h*32+d]
__device__ __align__(16) float g_kT[16 * 32 * 512];    // [(b*8+h)][d][j]
__device__ __align__(16) float g_v [BNq * 256];        // [bi][h*32+d]
__device__ __align__(16) float g_w [BNq * 8 * 256];    // [bi][h][c], pre-scaled
__device__ __align__(16) float g_attn[16 * 512 * 512]; // [(b*8+h)][i][j], scaled qk
__device__ __align__(16) float g_oi[BNq * 256];        // inner output before Wo

// ---- cp.async + f32x2 helpers ---------------------------------------------
__device__ __forceinline__ unsigned sptr(const void* p) {
    return (unsigned)__cvta_generic_to_shared(p);
}
#define CPA16(dst, src) asm volatile("cp.async.cg.shared.global [%0], [%1], 16;" :: "r"(dst), "l"(src))
#define CPA_COMMIT()    asm volatile("cp.async.commit_group;")
#define CPA_WAIT0()     asm volatile("cp.async.wait_group 0;")

__device__ __forceinline__ void ffma2(ull& d, ull a, ull b) {
    asm("fma.rn.f32x2 %0, %1, %2, %0;" : "+l"(d) : "l"(a), "l"(b));
}
__device__ __forceinline__ ull add2(ull a, ull b) {
    ull r; asm("add.rn.f32x2 %0, %1, %2;" : "=l"(r) : "l"(a), "l"(b)); return r;
}
__device__ __forceinline__ float2 unpk(ull v) {
    unsigned lo, hi;
    asm("mov.b64 {%0, %1}, %2;" : "=r"(lo), "=r"(hi) : "l"(v));
    float2 r; r.x = __uint_as_float(lo); r.y = __uint_as_float(hi); return r;
}
__device__ __forceinline__ ull dup2(float x) {
    unsigned xi = __float_as_uint(x);
    ull r; asm("mov.b64 %0, {%1, %1};" : "=l"(r) : "r"(xi)); return r;
}

// ---------------- kernel 1: q/k/v projections (16 rows/block) --------------
// grid (3, 64), 256 threads.
__global__ void __launch_bounds__(256) k_proj(const float* __restrict__ nodes,
                                              const float* __restrict__ Wq,
                                              const float* __restrict__ bq,
                                              const float* __restrict__ Wkv,
                                              const float* __restrict__ bkv) {
    __shared__ float rows[16 * 256];
    int t = threadIdx.x;
    int r0 = blockIdx.y * 16;
    #pragma unroll
    for (int r = 0; r < 16; ++r) rows[r * 256 + t] = nodes[(r0 + r) * 256 + t];
    __syncthreads();

    int colg = blockIdx.x * 256 + t;   // 0..767
    const float* W; int col, ldw;
    if (colg < 256) { W = Wq;  col = colg;       ldw = 256; }
    else            { W = Wkv; col = colg - 256; ldw = 512; }

    float acc[16];
    #pragma unroll
    for (int r = 0; r < 16; ++r) acc[r] = 0.f;

    for (int c = 0; c < 256; c += 4) {
        float w0 = W[(c + 0) * ldw + col];
        float w1 = W[(c + 1) * ldw + col];
        float w2 = W[(c + 2) * ldw + col];
        float w3 = W[(c + 3) * ldw + col];
        #pragma unroll
        for (int r = 0; r < 16; ++r) {
            float4 rv = *(const float4*)&rows[r * 256 + c];
            acc[r] += rv.x * w0 + rv.y * w1 + rv.z * w2 + rv.w * w3;
        }
    }

    if (colg < 256) {
        float bias = bq[col];
        #pragma unroll
        for (int r = 0; r < 16; ++r) g_q[(r0 + r) * 256 + col] = acc[r] + bias;
    } else if (col < 256) {           // k -> transposed layout
        float bias = bkv[col];
        int h = col >> 5, d = col & 31;
        #pragma unroll
        for (int r = 0; r < 16; ++r) {
            int row = r0 + r;
            g_kT[(((row >> 9) << 3) + h) * 16384 + d * 512 + (row & 511)] = acc[r] + bias;
        }
    } else {                          // v
        float bias = bkv[col];
        int c2 = col - 256;
        #pragma unroll
        for (int r = 0; r < 16; ++r) g_v[(r0 + r) * 256 + c2] = acc[r] + bias;
    }
}

// ---------------- kernel 2: w[bi][h][c] = SCALEF * sum_d We[c,hd]*q[bi,hd] -
__global__ void __launch_bounds__(256) k_w(const float* __restrict__ We) {
    __shared__ float We_s[32 * 257];  // [d][c], padded
    __shared__ float q_s[64 * 32];    // [r][d]
    int t = threadIdx.x;
    int h = blockIdx.y;
    int r0 = blockIdx.x * 64;

    #pragma unroll
    for (int k = 0; k < 32; ++k) {
        int lin = t + 256 * k;
        int c = lin >> 5, d = lin & 31;
        We_s[d * 257 + c] = We[c * 256 + h * 32 + d];
    }
    #pragma unroll
    for (int k = 0; k < 8; ++k) {
        int lin = t + 256 * k;
        int r = lin >> 5, d = lin & 31;
        q_s[lin] = g_q[(r0 + r) * 256 + h * 32 + d];
    }
    __syncthreads();

    float wrg[32];
    #pragma unroll
    for (int d = 0; d < 32; ++d) wrg[d] = We_s[d * 257 + t];

    for (int r = 0; r < 64; ++r) {
        float a0 = 0.f, a1 = 0.f, a2 = 0.f, a3 = 0.f;
        #pragma unroll
        for (int d4 = 0; d4 < 8; ++d4) {
            float4 qv = *(const float4*)&q_s[r * 32 + 4 * d4];
            a0 += qv.x * wrg[4 * d4 + 0];
            a1 += qv.y * wrg[4 * d4 + 1];
            a2 += qv.z * wrg[4 * d4 + 2];
            a3 += qv.w * wrg[4 * d4 + 3];
        }
        g_w[((r0 + r) * 8 + h) * 256 + t] = ((a0 + a1) + (a2 + a3)) * SCALEF;
    }
}

// ---------------- kernel 3: qk (pre-scaled by SCALEF), 16 i-rows/block -----
__global__ void __launch_bounds__(256) k_qk() {
    __shared__ float q_s[16 * 32];
    int t = threadIdx.x;
    int bh = blockIdx.y;
    int b = bh >> 3, h = bh & 7;
    int i0 = blockIdx.x * 16;

    #pragma unroll
    for (int x = 0; x < 2; ++x) {
        int lin = t + 256 * x;
        int r = lin >> 5, d = lin & 31;
        q_s[lin] = g_q[(b * 512 + i0 + r) * 256 + h * 32 + d];
    }
    __syncthreads();

    const float* kt = g_kT + bh * 16384;
    int j0 = 2 * t;
    float accA[16], accB[16];
    #pragma unroll
    for (int r = 0; r < 16; ++r) { accA[r] = 0.f; accB[r] = 0.f; }

    #pragma unroll
    for (int dk = 0; dk < 8; ++dk) {
        float2 k0 = *(const float2*)&kt[(4 * dk + 0) * 512 + j0];
        float2 k1 = *(const float2*)&kt[(4 * dk + 1) * 512 + j0];
        float2 k2 = *(const float2*)&kt[(4 * dk + 2) * 512 + j0];
        float2 k3 = *(const float2*)&kt[(4 * dk + 3) * 512 + j0];
        #pragma unroll
        for (int r = 0; r < 16; ++r) {
            float4 qv = *(const float4*)&q_s[r * 32 + 4 * dk];
            accA[r] += qv.x * k0.x + qv.y * k1.x + qv.z * k2.x + qv.w * k3.x;
            accB[r] += qv.x * k0.y + qv.y * k1.y + qv.z * k2.y + qv.w * k3.y;
        }
    }
    #pragma unroll
    for (int r = 0; r < 16; ++r) {
        float2 o; o.x = accA[r] * SCALEF; o.y = accB[r] * SCALEF;
        *(float2*)&g_attn[((size_t)(bh * 512) + i0 + r) * 512 + j0] = o;
    }
}

// ---------------- kernel 4: FUSED edge-dot + softmax + weighted sums -------
// grid 1024 (block per (b,i)), 256 threads, f32x2 packed math.
// Pass A (unchanged layout): warp wp owns rows {wp, wp+8}; 8-lane group g
//   handles heads {2g,2g+1}; lane s covers c = 32m+4s.  Lane s==0 also
//   accumulates softmax denominators (moved out of pass B).
// Pass B (restructured, LSU-light): thread (p = t>>7, q = t&127) owns
//   c-pair (2q,2q+1) and row-half jl in [8p, 8p+8).  Per (tile,jl):
//   1 LDS.64 edge + 2 LDS.128 p (broadcast) + 1 LDG.64 v; p for the
//   v-product is extracted from registers (no scalar p_s reads).
//   u/ov accumulators persist across tiles; halves merged once at the end.
__global__ void __launch_bounds__(256, 2) k_fused(const float* __restrict__ edges,
                                                  const float* __restrict__ We,
                                                  const float* __restrict__ be) {
    __shared__ __align__(16) float ebuf[2][4096];   // tiles; reused for merge staging
    __shared__ __align__(16) float qk_s[4096];      // [j][h]; reused for u_final/ov_final
    __shared__ __align__(16) float p_s[128];        // [jl][h]
    __shared__ float s_s[8];
    __shared__ float s_part[8][8];                  // [wp][h]

    int bi = blockIdx.x;
    int b = bi >> 9, i = bi & 511;
    int t = threadIdx.x, wp = t >> 5, l = t & 31, g = l >> 3, s = l & 7;
    int h0 = 2 * g;
    int pgrp = t >> 7;          // 0/1 : which 8-row half of each tile
    int q = t & 127;            // c-pair index: c = 2q, 2q+1
    int hq = q >> 4;            // head of inner indices (2q, 2q+1)

    // stage qk[j][h] (already SCALEF-scaled) — coalesced over j
    const float* qkb = g_attn + (size_t)(b * 8) * 262144 + (size_t)i * 512;
    #pragma unroll
    for (int x = 0; x < 16; ++x) {
        int lin = t + 256 * x;
        int h = lin >> 9, j = lin & 511;
        qk_s[j * 8 + h] = qkb[h * 262144 + j];
    }

    // pass-A weights as b64 (even,odd) pairs
    const float* wg = g_w + bi * 2048;
    ull wrp[2][8][2];
    #pragma unroll
    for (int hh = 0; hh < 2; ++hh)
        #pragma unroll
        for (int m = 0; m < 8; ++m) {
            ulonglong2 wv = *(const ulonglong2*)&wg[(h0 + hh) * 256 + 32 * m + 4 * s];
            wrp[hh][m][0] = wv.x; wrp[hh][m][1] = wv.y;
        }

    const float4* esrc = (const float4*)(edges + (size_t)bi * 131072);
    const float*  vb   = g_v + b * 131072;

    // prologue: stage tile 0
    #pragma unroll
    for (int k = 0; k < 4; ++k)
        CPA16(sptr(&ebuf[0][(t + 256 * k) * 4]), esrc + t + 256 * k);
    CPA_COMMIT();
    CPA_WAIT0();
    __syncthreads();    // covers tile0 + qk_s

    // persistent accumulators: uacc[ci*4+hp] = (u[2q+ci][2hp], u[2q+ci][2hp+1])
    ull uacc[8];
    #pragma unroll
    for (int k = 0; k < 8; ++k) uacc[k] = 0;
    ull ovacc = 0;
    float sacc0 = 0.f, sacc1 = 0.f;   // meaningful at lane s==0 only

    for (int tl = 0; tl < 32; ++tl) {
        int cur = tl & 1;
        if (tl < 31) {
            const float4* src = esrc + (tl + 1) * 1024;
            #pragma unroll
            for (int k = 0; k < 4; ++k)
                CPA16(sptr(&ebuf[cur ^ 1][(t + 256 * k) * 4]), src + t + 256 * k);
            CPA_COMMIT();
        }
        const float* eb = ebuf[cur];

        // ---- pass A ----
        #pragma unroll
        for (int rep = 0; rep < 2; ++rep) {
            int jl = wp + 8 * rep;
            const float* er = eb + jl * 256;
            ull aA = 0, aB = 0, bA = 0, bB = 0;
            #pragma unroll
            for (int m = 0; m < 8; ++m) {
                ulonglong2 ev = *(const ulonglong2*)&er[32 * m + 4 * s];
                ffma2(aA, ev.x, wrp[0][m][0]);
                ffma2(aB, ev.y, wrp[0][m][1]);
                ffma2(bA, ev.x, wrp[1][m][0]);
                ffma2(bB, ev.y, wrp[1][m][1]);
            }
            float2 f0 = unpk(add2(aA, aB));
            float2 f1 = unpk(add2(bA, bB));
            float s0 = f0.x + f0.y, s1 = f1.x + f1.y;
            #pragma unroll
            for (int off = 4; off; off >>= 1) {
                s0 += __shfl_xor_sync(0xffffffffu, s0, off);
                s1 += __shfl_xor_sync(0xffffffffu, s1, off);
            }
            if (s == 0) {
                int jg = tl * 16 + jl;
                float p0 = __expf(s0 + qk_s[jg * 8 + h0]);
                float p1 = __expf(s1 + qk_s[jg * 8 + h0 + 1]);
                p_s[jl * 8 + h0]     = p0;
                p_s[jl * 8 + h0 + 1] = p1;
                sacc0 += p0;
                sacc1 += p1;
            }
        }
        __syncthreads();   // p_s ready

        // ---- pass B (jl-split) ----
        const float* vbt = vb + tl * 4096;
        #pragma unroll
        for (int jj = 0; jj < 8; ++jj) {
            int jl = 8 * pgrp + jj;
            ulonglong2 pA = *(const ulonglong2*)&p_s[jl * 8];
            ulonglong2 pB = *(const ulonglong2*)&p_s[jl * 8 + 4];
            float2 e2 = *(const float2*)&eb[jl * 256 + 2 * q];
            ull e0 = dup2(e2.x), e1 = dup2(e2.y);
            ffma2(uacc[0], pA.x, e0); ffma2(uacc[1], pA.y, e0);
            ffma2(uacc[2], pB.x, e0); ffma2(uacc[3], pB.y, e0);
            ffma2(uacc[4], pA.x, e1); ffma2(uacc[5], pA.y, e1);
            ffma2(uacc[6], pB.x, e1); ffma2(uacc[7], pB.y, e1);
            // ov: v pair, p extracted from registers (no smem read)
            ull vvu = *(const ull*)&vbt[jl * 256 + 2 * q];
            ull selp = (hq & 4) ? ((hq & 2) ? pB.y : pB.x)
                                : ((hq & 2) ? pA.y : pA.x);
            float2 sv = unpk(selp);
            float ph = (hq & 1) ? sv.y : sv.x;
            ffma2(ovacc, vvu, dup2(ph));
        }

        if (tl < 31) CPA_WAIT0();
        __syncthreads();
    }

    // ---- softmax denominators ----
    if (s == 0) { s_part[wp][h0] = sacc0; s_part[wp][h0 + 1] = sacc1; }
    // ---- stage pgrp==0 partials (ebuf free: last tile used ebuf[1]) -------
    ull* ustage  = (ull*)&ebuf[0][0];      // 128 q x 8 ull
    ull* ovstage = (ull*)&ebuf[0][2048];   // 128 ull
    if (pgrp == 0) {
        #pragma unroll
        for (int k = 0; k < 8; ++k) ustage[q * 8 + k] = uacc[k];
        ovstage[q] = ovacc;
    }
    __syncthreads();
    if (t < 8) {
        float ss = 0.f;
        #pragma unroll
        for (int w = 0; w < 8; ++w) ss += s_part[w][t];
        s_s[t] = ss;
    }
    __syncthreads();

    float* u_final  = qk_s;          // [h*256+c], 2048 floats (qk_s done)
    float* ov_final = qk_s + 2048;   // 256 floats
    if (pgrp == 1) {
        #pragma unroll
        for (int k = 0; k < 8; ++k) uacc[k] = add2(uacc[k], ustage[q * 8 + k]);
        ovacc = add2(ovacc, ovstage[q]);
        #pragma unroll
        for (int hp = 0; hp < 4; ++hp) {
            float2 c0v = unpk(uacc[hp]);
            float2 c1v = unpk(uacc[4 + hp]);
            float inv0 = 1.0f / s_s[2 * hp];
            float inv1 = 1.0f / s_s[2 * hp + 1];
            u_final[(2 * hp)     * 256 + 2 * q]     = c0v.x * inv0;
            u_final[(2 * hp + 1) * 256 + 2 * q]     = c0v.y * inv1;
            u_final[(2 * hp)     * 256 + 2 * q + 1] = c1v.x * inv0;
            u_final[(2 * hp + 1) * 256 + 2 * q + 1] = c1v.y * inv1;
        }
        float2 ovv = unpk(ovacc);
        float invh = 1.0f / s_s[hq];
        ov_final[2 * q]     = ovv.x * invh;
        ov_final[2 * q + 1] = ovv.y * invh;
    }
    __syncthreads();

    // tail: out_inner[t] = ov + (u[hw] @ We)[t] + be[t]
    int hw = t >> 5;
    float p0 = 0.f, p1 = 0.f, p2 = 0.f, p3 = 0.f;
    for (int c = 0; c < 256; c += 4) {
        float4 uv = *(const float4*)&u_final[hw * 256 + c];
        p0 += uv.x * We[(c + 0) * 256 + t];
        p1 += uv.y * We[(c + 1) * 256 + t];
        p2 += uv.z * We[(c + 2) * 256 + t];
        p3 += uv.w * We[(c + 3) * 256 + t];
    }
    g_oi[bi * 256 + t] = ov_final[t] + ((p0 + p1) + (p2 + p3)) + be[t];
}

// ---------------- kernel 5: final out = oi @ Wo + bo (8 rows/block) --------
__global__ void __launch_bounds__(256) k_final(const float* __restrict__ Wo,
                                               const float* __restrict__ bo,
                                               float* __restrict__ out) {
    __shared__ float rows[8 * 256];
    int t = threadIdx.x;
    int r0 = blockIdx.x * 8;
    #pragma unroll
    for (int r = 0; r < 8; ++r) rows[r * 256 + t] = g_oi[(r0 + r) * 256 + t];
    __syncthreads();

    float a[8];
    #pragma unroll
    for (int r = 0; r < 8; ++r) a[r] = 0.f;
    for (int c = 0; c < 256; c += 4) {
        float w0 = Wo[(c + 0) * 256 + t];
        float w1 = Wo[(c + 1) * 256 + t];
        float w2 = Wo[(c + 2) * 256 + t];
        float w3 = Wo[(c + 3) * 256 + t];
        #pragma unroll
        for (int r = 0; r < 8; ++r) {
            float4 rv = *(const float4*)&rows[r * 256 + c];
            a[r] += rv.x * w0 + rv.y * w1 + rv.z * w2 + rv.w * w3;
        }
    }
    float bb = bo[t];
    #pragma unroll
    for (int r = 0; r < 8; ++r) out[(r0 + r) * 256 + t] = a[r] + bb;
}

// ---------------- launch ----------------------------------------------------
extern "C" void kernel_launch(void* const* d_in, const int* in_sizes, int n_in,
                              void* d_out, int out_size) {
    (void)in_sizes; (void)n_in; (void)out_size;
    const float* nodes = (const float*)d_in[0];
    const float* edges = (const float*)d_in[1];
    const float* Wq    = (const float*)d_in[2];
    const float* bq    = (const float*)d_in[3];
    const float* Wkv   = (const float*)d_in[4];
    const float* bkv   = (const float*)d_in[5];
    const float* We    = (const float*)d_in[6];
    const float* be    = (const float*)d_in[7];
    const float* Wo    = (const float*)d_in[8];
    const float* bo    = (const float*)d_in[9];
    float* out = (float*)d_out;

    k_proj <<<dim3(3, 64),  256>>>(nodes, Wq, bq, Wkv, bkv);
    k_w    <<<dim3(16, 8),  256>>>(We);
    k_qk   <<<dim3(32, 16), 256>>>();
    k_fused<<<1024,         256>>>(edges, We, be);
    k_final<<<128,          256>>>(Wo, bo, out);
}